// round 2
// baseline (speedup 1.0000x reference)
#include <cuda_runtime.h>

#define NMAX   1024
#define DDIM   128
#define MARGIN 1.9f

// Scratch (no allocation allowed)
__device__ float g_dist[NMAX * NMAX];
__device__ float g_psum[NMAX];
__device__ int   g_pcnt[NMAX];
__device__ int   g_pvalid[NMAX];
__device__ int   g_lab[NMAX];
__device__ int   g_bar1 = 0;   // dist-done barrier
__device__ int   g_bar2 = 0;   // triplet-done counter (last block finalizes + resets)

// Single fused kernel:
//   phase 0: block 0 normalizes labels (int64 -> int32)
//   phase 1: blocks 0..ntiles-1 compute 32x32 dist tiles
//   grid barrier (all 640 blocks resident by construction)
//   phase 2: block b = triplet accumulation for anchor b
//   phase 3: last-finishing block reduces partials -> out[4], resets counters
__global__ void __launch_bounds__(256, 5)
fused_triplet_kernel(const float* __restrict__ e, const int* __restrict__ lab32,
                     float* __restrict__ out, int n) {
    // 32 KB shared, reused across phases:
    //  phase 1: As[32][128] (16KB) + Bs[128][32] (16KB)
    //  phase 2: pos_d[1024] (4KB) + neg_d[1024] (4KB)
    __shared__ float sbuf[32 * DDIM + DDIM * 32];
    __shared__ int   sp, sn, s_old;
    __shared__ float wsum[8];
    __shared__ int   wcnt[8];
    __shared__ int   s_is64;

    const int b    = blockIdx.x;
    const int tid  = threadIdx.x;
    const int lane = tid & 31;
    const int wid  = tid >> 5;

    // ---------- phase 0: labels (block 0 only) ----------
    if (b == 0) {
        if (tid == 0) s_is64 = 1;
        __syncthreads();
        for (int idx = tid; idx < n / 2; idx += 256) {
            if (lab32[2 * idx + 1] != 0) atomicExch(&s_is64, 0);
        }
        __syncthreads();
        const bool is64 = (s_is64 != 0);
        for (int i2 = tid; i2 < n; i2 += 256) {
            g_lab[i2] = is64 ? lab32[2 * i2] : lab32[i2];
        }
    }

    // ---------- phase 1: dist tile ----------
    const int tiles_x = n >> 5;            // 20
    const int ntiles  = tiles_x * tiles_x; // 400
    if (b < ntiles) {
        float (*As)[DDIM] = (float (*)[DDIM])sbuf;            // As[32][128]
        float (*Bs)[32]   = (float (*)[32])(sbuf + 32 * DDIM); // Bs[128][32]
        const int bi = (b / tiles_x) * 32;
        const int bj = (b % tiles_x) * 32;
        const float4* e4 = (const float4*)e;  // 32 float4 per row

        #pragma unroll
        for (int r = 0; r < 4; r++) {
            int lin = tid + r * 256;
            int row = lin >> 5;
            int c4  = lin & 31;
            float4 v = e4[(size_t)(bi + row) * 32 + c4];
            *(float4*)&As[row][c4 * 4] = v;
        }
        #pragma unroll
        for (int r = 0; r < 4; r++) {
            int lin = tid + r * 256;
            int j   = lin & 31;             // lane-varying -> conflict-free stores
            int c4  = lin >> 5;
            float4 v = e4[(size_t)(bj + j) * 32 + c4];
            Bs[c4 * 4 + 0][j] = v.x;
            Bs[c4 * 4 + 1][j] = v.y;
            Bs[c4 * 4 + 2][j] = v.z;
            Bs[c4 * 4 + 3][j] = v.w;
        }
        __syncthreads();

        const int tx = tid & 31;
        const int ty = tid >> 5;
        float a0 = 0.f, a1 = 0.f, a2 = 0.f, a3 = 0.f;
        #pragma unroll 4
        for (int k = 0; k < DDIM; k++) {
            float bb = Bs[k][tx];
            float d0 = As[ty +  0][k] - bb;
            float d1 = As[ty +  8][k] - bb;
            float d2 = As[ty + 16][k] - bb;
            float d3 = As[ty + 24][k] - bb;
            a0 = fmaf(d0, d0, a0);
            a1 = fmaf(d1, d1, a1);
            a2 = fmaf(d2, d2, a2);
            a3 = fmaf(d3, d3, a3);
        }
        int jc = bj + tx;
        g_dist[(size_t)(bi + ty +  0) * n + jc] = sqrtf(a0);
        g_dist[(size_t)(bi + ty +  8) * n + jc] = sqrtf(a1);
        g_dist[(size_t)(bi + ty + 16) * n + jc] = sqrtf(a2);
        g_dist[(size_t)(bi + ty + 24) * n + jc] = sqrtf(a3);
    }

    // ---------- grid barrier ----------
    __threadfence();           // publish dist tiles + labels
    __syncthreads();
    if (tid == 0) {
        atomicAdd(&g_bar1, 1);
        volatile int* vb = &g_bar1;
        while (*vb < gridDim.x) { /* spin */ }
    }
    __syncthreads();           // all threads see barrier passed; smem reuse safe

    // ---------- phase 2: triplet for anchor i = b ----------
    float* pos_d = sbuf;           // [<=1024]
    float* neg_d = sbuf + NMAX;    // [<=1024]
    const unsigned lmask_lt = (1u << lane) - 1u;

    if (tid == 0) { sp = 0; sn = 0; }
    __syncthreads();

    const int i  = b;
    const int li = g_lab[i];
    const float* __restrict__ drow = &g_dist[(size_t)i * n];

    for (int base = wid * 32; base < n; base += 256) {
        int j = base + lane;
        bool inb = (j < n) && (j != i);
        float dv = 0.f;
        int lj = 0;
        if (inb) { dv = drow[j]; lj = g_lab[j]; }
        bool isp = inb && (lj == li);
        bool isn = inb && (lj != li);
        unsigned mp = __ballot_sync(0xFFFFFFFFu, isp);
        unsigned mn = __ballot_sync(0xFFFFFFFFu, isn);
        int bp = 0, bn = 0;
        if (lane == 0) {
            if (mp) bp = atomicAdd(&sp, __popc(mp));
            if (mn) bn = atomicAdd(&sn, __popc(mn));
        }
        bp = __shfl_sync(0xFFFFFFFFu, bp, 0);
        bn = __shfl_sync(0xFFFFFFFFu, bn, 0);
        if (isp) pos_d[bp + __popc(mp & lmask_lt)] = dv;
        if (isn) neg_d[bn + __popc(mn & lmask_lt)] = dv;
    }
    __syncthreads();

    const int P  = sp;
    const int Nn = sn;

    const float SENT = 3.0e38f;
    float nk0 = (tid       < Nn) ? neg_d[tid]       : SENT;
    float nk1 = (tid + 256 < Nn) ? neg_d[tid + 256] : SENT;
    float nk2 = (tid + 512 < Nn) ? neg_d[tid + 512] : SENT;
    float nk3 = (tid + 768 < Nn) ? neg_d[tid + 768] : SENT;

    float lsum = 0.f;
    int   lcnt = 0;
    for (int j = 0; j < P; j++) {
        float t0 = pos_d[j] + MARGIN;        // broadcast LDS
        if (nk0 < t0) { lsum += t0 - nk0; lcnt++; }
        if (nk1 < t0) { lsum += t0 - nk1; lcnt++; }
        if (nk2 < t0) { lsum += t0 - nk2; lcnt++; }
        if (nk3 < t0) { lsum += t0 - nk3; lcnt++; }
    }

    #pragma unroll
    for (int off = 16; off; off >>= 1) {
        lsum += __shfl_down_sync(0xFFFFFFFFu, lsum, off);
        lcnt += __shfl_down_sync(0xFFFFFFFFu, lcnt, off);
    }
    if (lane == 0) { wsum[wid] = lsum; wcnt[wid] = lcnt; }
    __syncthreads();
    if (tid == 0) {
        float s = 0.f; int c = 0;
        #pragma unroll
        for (int w = 0; w < 8; w++) { s += wsum[w]; c += wcnt[w]; }
        g_psum[i]   = s;
        g_pcnt[i]   = c;
        g_pvalid[i] = P * Nn;
    }

    // ---------- phase 3: last block finalizes ----------
    __threadfence();           // publish this block's partials
    __syncthreads();
    if (tid == 0) s_old = atomicAdd(&g_bar2, 1);
    __syncthreads();
    if (s_old == (int)gridDim.x - 1) {
        // we are last: all partials are globally visible
        float s = 0.f;
        long long c = 0, v = 0;
        for (int idx = tid; idx < n; idx += 256) {
            s += g_psum[idx];
            c += (long long)g_pcnt[idx];
            v += (long long)g_pvalid[idx];
        }
        #pragma unroll
        for (int off = 16; off; off >>= 1) {
            s += __shfl_down_sync(0xFFFFFFFFu, s, off);
            c += __shfl_down_sync(0xFFFFFFFFu, c, off);
            v += __shfl_down_sync(0xFFFFFFFFu, v, off);
        }
        __shared__ float fs[8];
        __shared__ long long fc[8], fv[8];
        if (lane == 0) { fs[wid] = s; fc[wid] = c; fv[wid] = v; }
        __syncthreads();
        if (tid == 0) {
            float total = 0.f;
            long long cnt = 0, val = 0;
            #pragma unroll
            for (int w = 0; w < 8; w++) { total += fs[w]; cnt += fc[w]; val += fv[w]; }
            float num_non   = (float)cnt;
            float num_valid = (float)val;
            out[0] = (cnt > 0) ? total / fmaxf(num_non, 1.0f) : 0.0f;
            out[1] = num_valid;
            out[2] = num_non;
            out[3] = num_non / (num_valid + 1e-16f);
            // reset barriers for next graph replay (stream-ordered visibility)
            g_bar1 = 0;
            g_bar2 = 0;
            __threadfence();
        }
    }
}

extern "C" void kernel_launch(void* const* d_in, const int* in_sizes, int n_in,
                              void* d_out, int out_size) {
    const float* e   = (const float*)d_in[0];   // embeddings [8,80,128] fp32
    const int*   lab = (const int*)d_in[1];     // labels (int64 or int32 view)
    int n = in_sizes[1];                        // 640 flattened anchors

    fused_triplet_kernel<<<n, 256>>>(e, lab, (float*)d_out, n);
}

// round 3
// speedup vs baseline: 1.0684x; 1.0684x over previous
#include <cuda_runtime.h>

#define MARGIN  1.9f
#define GRID    148
#define NMAXE   1024
#define BIGF    3.0e38f

// Scratch (no allocation allowed)
__device__ float g_dot[640 * 640];   // raw dot products (dist derived on the fly)
__device__ float g_sq[NMAXE];        // squared norms
__device__ int   g_lab[NMAXE];       // normalized labels
__device__ float g_bsum[GRID];
__device__ int   g_bcnt[GRID];
__device__ int   g_bval[GRID];
__device__ int   g_bar1 = 0;
__device__ int   g_bar2 = 0;

// One fused kernel, grid=148 (1 block/SM -> spin barrier trivially safe):
//  phase 1: blocks 0..99   : 64x64 dot tiles (4x4 micro, k chunked 2x64)
//           blocks 100..119: 32 row sq-norms each
//           block  120     : label normalization (int64 -> int32 autodetect)
//  grid barrier
//  phase 2: block b handles anchors i = b, b+148, ... (4-5 each)
//  phase 3: last block reduces per-block partials -> out[4], resets barriers
__global__ void __launch_bounds__(256)
fused_triplet_kernel(const float* __restrict__ e, const int* __restrict__ lab32,
                     float* __restrict__ out, int n) {
    __shared__ float As[64 * 68];    // row-major A chunk [row][k+pad]
    __shared__ float Bs[64 * 64];    // k-major   B chunk [k][col]
    __shared__ int   sp, s_old, s_is64;
    __shared__ float wsum[8];
    __shared__ int   wcnt[8];

    const int b    = blockIdx.x;
    const int tid  = threadIdx.x;
    const int lane = tid & 31;
    const int wid  = tid >> 5;
    const unsigned lmask_lt = (1u << lane) - 1u;
    const float4* e4 = (const float4*)e;   // 32 float4 per embedding row

    const int tiles_x     = n >> 6;              // 10
    const int dist_blocks = tiles_x * tiles_x;   // 100
    const int sq_blocks   = n >> 5;              // 20
    const int lab_block   = dist_blocks + sq_blocks;  // 120

    // ================= phase 1 =================
    if (b < dist_blocks) {
        const int ti = b / tiles_x;
        const int tj = b % tiles_x;
        const int tx = tid & 15;     // col group
        const int ty = tid >> 4;     // row group

        float acc[4][4];
        #pragma unroll
        for (int q = 0; q < 4; q++)
            #pragma unroll
            for (int r = 0; r < 4; r++) acc[q][r] = 0.f;

        #pragma unroll
        for (int ch = 0; ch < 2; ch++) {
            __syncthreads();
            // load A chunk: row-major [64][68], coalesced LDG.128 + conflict-free STS.128
            #pragma unroll
            for (int r = 0; r < 4; r++) {
                int lin = tid + r * 256;
                int row = lin >> 4;          // 0..63
                int c4  = lin & 15;          // 0..15
                float4 v = e4[(size_t)(ti * 64 + row) * 32 + ch * 16 + c4];
                *(float4*)&As[row * 68 + c4 * 4] = v;
            }
            // load B chunk transposed: k-major [64][64], conflict-free STS
            #pragma unroll
            for (int r = 0; r < 4; r++) {
                int lin = tid + r * 256;
                int j   = lin & 63;          // col, lane-varying
                int c4i = lin >> 6;          // 0..15
                float4 v = e4[(size_t)(tj * 64 + j) * 32 + ch * 16 + c4i];
                Bs[(c4i * 4 + 0) * 64 + j] = v.x;
                Bs[(c4i * 4 + 1) * 64 + j] = v.y;
                Bs[(c4i * 4 + 2) * 64 + j] = v.z;
                Bs[(c4i * 4 + 3) * 64 + j] = v.w;
            }
            __syncthreads();

            #pragma unroll 4
            for (int k = 0; k < 64; k++) {
                float4 bv = *(const float4*)&Bs[k * 64 + 4 * tx];
                float a0 = As[(4 * ty + 0) * 68 + k];
                float a1 = As[(4 * ty + 1) * 68 + k];
                float a2 = As[(4 * ty + 2) * 68 + k];
                float a3 = As[(4 * ty + 3) * 68 + k];
                acc[0][0] = fmaf(a0, bv.x, acc[0][0]);
                acc[0][1] = fmaf(a0, bv.y, acc[0][1]);
                acc[0][2] = fmaf(a0, bv.z, acc[0][2]);
                acc[0][3] = fmaf(a0, bv.w, acc[0][3]);
                acc[1][0] = fmaf(a1, bv.x, acc[1][0]);
                acc[1][1] = fmaf(a1, bv.y, acc[1][1]);
                acc[1][2] = fmaf(a1, bv.z, acc[1][2]);
                acc[1][3] = fmaf(a1, bv.w, acc[1][3]);
                acc[2][0] = fmaf(a2, bv.x, acc[2][0]);
                acc[2][1] = fmaf(a2, bv.y, acc[2][1]);
                acc[2][2] = fmaf(a2, bv.z, acc[2][2]);
                acc[2][3] = fmaf(a2, bv.w, acc[2][3]);
                acc[3][0] = fmaf(a3, bv.x, acc[3][0]);
                acc[3][1] = fmaf(a3, bv.y, acc[3][1]);
                acc[3][2] = fmaf(a3, bv.z, acc[3][2]);
                acc[3][3] = fmaf(a3, bv.w, acc[3][3]);
            }
        }
        // write raw dots (coalesced float4 per micro-row)
        #pragma unroll
        for (int q = 0; q < 4; q++) {
            int row = ti * 64 + 4 * ty + q;
            float4 o = make_float4(acc[q][0], acc[q][1], acc[q][2], acc[q][3]);
            *(float4*)&g_dot[(size_t)row * n + tj * 64 + 4 * tx] = o;
        }
    } else if (b < lab_block) {
        // sq norms: 32 rows per block, 4 rows per warp
        int r0 = (b - dist_blocks) * 32;
        #pragma unroll
        for (int it = 0; it < 4; it++) {
            int row = r0 + wid + it * 8;
            float4 v = e4[(size_t)row * 32 + lane];
            float s = v.x * v.x + v.y * v.y + v.z * v.z + v.w * v.w;
            #pragma unroll
            for (int off = 16; off; off >>= 1)
                s += __shfl_down_sync(0xFFFFFFFFu, s, off);
            if (lane == 0) g_sq[row] = s;
        }
    } else if (b == lab_block) {
        // labels: autodetect int64 vs int32 layout
        if (tid == 0) s_is64 = 1;
        __syncthreads();
        for (int idx = tid; idx < n / 2; idx += 256)
            if (lab32[2 * idx + 1] != 0) atomicExch(&s_is64, 0);
        __syncthreads();
        const bool is64 = (s_is64 != 0);
        for (int i2 = tid; i2 < n; i2 += 256)
            g_lab[i2] = is64 ? lab32[2 * i2] : lab32[i2];
    }

    // ================= grid barrier =================
    __threadfence();
    __syncthreads();
    if (tid == 0) {
        atomicAdd(&g_bar1, 1);
        volatile int* vb = &g_bar1;
        while (*vb < GRID) { }
    }
    __syncthreads();

    // ================= phase 2: anchors =================
    float* pos_d = As;               // reuse smem (<= 644+4 floats needed)
    float lsum = 0.f;
    int   lcnt = 0;
    int   vtot = 0;

    for (int i = b; i < n; i += GRID) {
        const int   li  = g_lab[i];
        const float sqi = g_sq[i];
        const float* __restrict__ drow = &g_dot[(size_t)i * n];

        // per-thread j slots: tid, tid+256, tid+512
        float nk0 = BIGF, nk1 = BIGF, nk2 = BIGF;
        float pv0 = 0.f, pv1 = 0.f, pv2 = 0.f;
        bool  ip0 = false, ip1 = false, ip2 = false;
        {
            int j = tid;
            float dv = sqrtf(fmaxf(sqi + g_sq[j] - 2.0f * drow[j], 0.0f));
            bool same = (g_lab[j] == li);
            nk0 = same ? BIGF : dv;
            ip0 = same && (j != i);
            pv0 = dv + MARGIN;
        }
        {
            int j = tid + 256;
            float dv = sqrtf(fmaxf(sqi + g_sq[j] - 2.0f * drow[j], 0.0f));
            bool same = (g_lab[j] == li);
            nk1 = same ? BIGF : dv;
            ip1 = same && (j != i);
            pv1 = dv + MARGIN;
        }
        if (tid + 512 < n) {
            int j = tid + 512;
            float dv = sqrtf(fmaxf(sqi + g_sq[j] - 2.0f * drow[j], 0.0f));
            bool same = (g_lab[j] == li);
            nk2 = same ? BIGF : dv;
            ip2 = same && (j != i);
            pv2 = dv + MARGIN;
        }

        __syncthreads();                   // prev anchor's P-loop done
        if (tid == 0) sp = 0;
        __syncthreads();

        // warp-aggregated append of positives (d + MARGIN)
        {
            unsigned m = __ballot_sync(0xFFFFFFFFu, ip0);
            if (m) {
                int base = 0;
                if (lane == 0) base = atomicAdd(&sp, __popc(m));
                base = __shfl_sync(0xFFFFFFFFu, base, 0);
                if (ip0) pos_d[base + __popc(m & lmask_lt)] = pv0;
            }
        }
        {
            unsigned m = __ballot_sync(0xFFFFFFFFu, ip1);
            if (m) {
                int base = 0;
                if (lane == 0) base = atomicAdd(&sp, __popc(m));
                base = __shfl_sync(0xFFFFFFFFu, base, 0);
                if (ip1) pos_d[base + __popc(m & lmask_lt)] = pv1;
            }
        }
        {
            unsigned m = __ballot_sync(0xFFFFFFFFu, ip2);
            if (m) {
                int base = 0;
                if (lane == 0) base = atomicAdd(&sp, __popc(m));
                base = __shfl_sync(0xFFFFFFFFu, base, 0);
                if (ip2) pos_d[base + __popc(m & lmask_lt)] = pv2;
            }
        }
        __syncthreads();
        const int P = sp;
        if (tid < 4) pos_d[P + tid] = -BIGF;    // sentinel pad for 4-wide loop
        __syncthreads();

        for (int jj = 0; jj < P; jj += 4) {
            float4 t = *(const float4*)&pos_d[jj];   // broadcast LDS.128
            if (nk0 < t.x) { lsum += t.x - nk0; lcnt++; }
            if (nk1 < t.x) { lsum += t.x - nk1; lcnt++; }
            if (nk2 < t.x) { lsum += t.x - nk2; lcnt++; }
            if (nk0 < t.y) { lsum += t.y - nk0; lcnt++; }
            if (nk1 < t.y) { lsum += t.y - nk1; lcnt++; }
            if (nk2 < t.y) { lsum += t.y - nk2; lcnt++; }
            if (nk0 < t.z) { lsum += t.z - nk0; lcnt++; }
            if (nk1 < t.z) { lsum += t.z - nk1; lcnt++; }
            if (nk2 < t.z) { lsum += t.z - nk2; lcnt++; }
            if (nk0 < t.w) { lsum += t.w - nk0; lcnt++; }
            if (nk1 < t.w) { lsum += t.w - nk1; lcnt++; }
            if (nk2 < t.w) { lsum += t.w - nk2; lcnt++; }
        }
        vtot += P * (n - 1 - P);
    }

    // block reduce
    #pragma unroll
    for (int off = 16; off; off >>= 1) {
        lsum += __shfl_down_sync(0xFFFFFFFFu, lsum, off);
        lcnt += __shfl_down_sync(0xFFFFFFFFu, lcnt, off);
    }
    if (lane == 0) { wsum[wid] = lsum; wcnt[wid] = lcnt; }
    __syncthreads();
    if (tid == 0) {
        float s = 0.f; int c = 0;
        #pragma unroll
        for (int w = 0; w < 8; w++) { s += wsum[w]; c += wcnt[w]; }
        g_bsum[b] = s;
        g_bcnt[b] = c;
        g_bval[b] = vtot;
    }

    // ================= phase 3: last block finalizes =================
    __threadfence();
    __syncthreads();
    if (tid == 0) s_old = atomicAdd(&g_bar2, 1);
    __syncthreads();
    if (s_old == GRID - 1) {
        float s = 0.f; int c = 0, v = 0;
        if (tid < GRID) { s = g_bsum[tid]; c = g_bcnt[tid]; v = g_bval[tid]; }
        #pragma unroll
        for (int off = 16; off; off >>= 1) {
            s += __shfl_down_sync(0xFFFFFFFFu, s, off);
            c += __shfl_down_sync(0xFFFFFFFFu, c, off);
            v += __shfl_down_sync(0xFFFFFFFFu, v, off);
        }
        __shared__ float fs[8];
        __shared__ int   fc[8], fv[8];
        if (lane == 0) { fs[wid] = s; fc[wid] = c; fv[wid] = v; }
        __syncthreads();
        if (tid == 0) {
            float total = 0.f; int cnt = 0, val = 0;
            #pragma unroll
            for (int w = 0; w < 8; w++) { total += fs[w]; cnt += fc[w]; val += fv[w]; }
            float num_non   = (float)cnt;
            float num_valid = (float)val;
            out[0] = (cnt > 0) ? total / fmaxf(num_non, 1.0f) : 0.0f;
            out[1] = num_valid;
            out[2] = num_non;
            out[3] = num_non / (num_valid + 1e-16f);
            g_bar1 = 0;
            g_bar2 = 0;
            __threadfence();
        }
    }
}

extern "C" void kernel_launch(void* const* d_in, const int* in_sizes, int n_in,
                              void* d_out, int out_size) {
    const float* e   = (const float*)d_in[0];   // embeddings [8,80,128] fp32
    const int*   lab = (const int*)d_in[1];     // labels (int64 or int32 view)
    int n = in_sizes[1];                        // 640

    fused_triplet_kernel<<<GRID, 256>>>(e, lab, (float*)d_out, n);
}

// round 5
// speedup vs baseline: 1.3050x; 1.2215x over previous
#include <cuda_runtime.h>

#define MARGIN  1.9f
#define GRID    592              // 4 blocks per SM (148 SMs), all resident in wave 1
#define NMAXE   1024
#define BIGF    3.0e38f

// Scratch (no allocation allowed)
__device__ float g_dot[640 * 640];   // raw dot products
__device__ float g_sq[NMAXE];        // squared norms
__device__ int   g_lab[NMAXE];       // normalized labels
__device__ float g_bsum[GRID];
__device__ int   g_bcnt[GRID];
__device__ int   g_bval[GRID];
__device__ int   g_bar1 = 0;
__device__ int   g_bar2 = 0;

// Fused kernel, grid=592 (=4/SM, spin barrier safe by construction):
//  phase 1: blocks 0..99   : 64x64 dot tiles (4x4 micro, k chunked 2x64)
//           blocks 100..119: 32 row sq-norms each
//           block  120     : label normalization; blocks 121..591 idle
//  grid barrier
//  phase 2: block b handles anchors i = b, b+592 (1-2 each)
//  phase 3: last block reduces per-block partials -> out[4], resets barriers
__global__ void __launch_bounds__(256, 4)
fused_triplet_kernel(const float* __restrict__ e, const int* __restrict__ lab32,
                     float* __restrict__ out, int n) {
    __shared__ float As[64 * 68];    // 17.4 KB
    __shared__ float Bs[64 * 64];    // 16 KB
    __shared__ int   sp, s_old, s_is64;
    __shared__ float wsum[8];
    __shared__ int   wcnt[8];

    const int b    = blockIdx.x;
    const int tid  = threadIdx.x;
    const int lane = tid & 31;
    const int wid  = tid >> 5;
    const unsigned lmask_lt = (1u << lane) - 1u;
    const float4* e4 = (const float4*)e;

    const int tiles_x     = n >> 6;                   // 10
    const int dist_blocks = tiles_x * tiles_x;        // 100
    const int sq_blocks   = n >> 5;                   // 20
    const int lab_block   = dist_blocks + sq_blocks;  // 120

    // ================= phase 1 =================
    if (b < dist_blocks) {
        const int ti = b / tiles_x;
        const int tj = b % tiles_x;
        const int tx = tid & 15;
        const int ty = tid >> 4;

        float acc[4][4];
        #pragma unroll
        for (int q = 0; q < 4; q++)
            #pragma unroll
            for (int r = 0; r < 4; r++) acc[q][r] = 0.f;

        #pragma unroll
        for (int ch = 0; ch < 2; ch++) {
            __syncthreads();
            #pragma unroll
            for (int r = 0; r < 4; r++) {
                int lin = tid + r * 256;
                int row = lin >> 4;
                int c4  = lin & 15;
                float4 v = e4[(size_t)(ti * 64 + row) * 32 + ch * 16 + c4];
                *(float4*)&As[row * 68 + c4 * 4] = v;
            }
            #pragma unroll
            for (int r = 0; r < 4; r++) {
                int lin = tid + r * 256;
                int j   = lin & 63;
                int c4i = lin >> 6;
                float4 v = e4[(size_t)(tj * 64 + j) * 32 + ch * 16 + c4i];
                Bs[(c4i * 4 + 0) * 64 + j] = v.x;
                Bs[(c4i * 4 + 1) * 64 + j] = v.y;
                Bs[(c4i * 4 + 2) * 64 + j] = v.z;
                Bs[(c4i * 4 + 3) * 64 + j] = v.w;
            }
            __syncthreads();

            #pragma unroll 4
            for (int k = 0; k < 64; k++) {
                float4 bv = *(const float4*)&Bs[k * 64 + 4 * tx];
                float a0 = As[(4 * ty + 0) * 68 + k];
                float a1 = As[(4 * ty + 1) * 68 + k];
                float a2 = As[(4 * ty + 2) * 68 + k];
                float a3 = As[(4 * ty + 3) * 68 + k];
                acc[0][0] = fmaf(a0, bv.x, acc[0][0]);
                acc[0][1] = fmaf(a0, bv.y, acc[0][1]);
                acc[0][2] = fmaf(a0, bv.z, acc[0][2]);
                acc[0][3] = fmaf(a0, bv.w, acc[0][3]);
                acc[1][0] = fmaf(a1, bv.x, acc[1][0]);
                acc[1][1] = fmaf(a1, bv.y, acc[1][1]);
                acc[1][2] = fmaf(a1, bv.z, acc[1][2]);
                acc[1][3] = fmaf(a1, bv.w, acc[1][3]);
                acc[2][0] = fmaf(a2, bv.x, acc[2][0]);
                acc[2][1] = fmaf(a2, bv.y, acc[2][1]);
                acc[2][2] = fmaf(a2, bv.z, acc[2][2]);
                acc[2][3] = fmaf(a2, bv.w, acc[2][3]);
                acc[3][0] = fmaf(a3, bv.x, acc[3][0]);
                acc[3][1] = fmaf(a3, bv.y, acc[3][1]);
                acc[3][2] = fmaf(a3, bv.z, acc[3][2]);
                acc[3][3] = fmaf(a3, bv.w, acc[3][3]);
            }
        }
        #pragma unroll
        for (int q = 0; q < 4; q++) {
            int row = ti * 64 + 4 * ty + q;
            float4 o = make_float4(acc[q][0], acc[q][1], acc[q][2], acc[q][3]);
            *(float4*)&g_dot[(size_t)row * n + tj * 64 + 4 * tx] = o;
        }
    } else if (b < lab_block) {
        int r0 = (b - dist_blocks) * 32;
        #pragma unroll
        for (int it = 0; it < 4; it++) {
            int row = r0 + wid + it * 8;
            float4 v = e4[(size_t)row * 32 + lane];
            float s = v.x * v.x + v.y * v.y + v.z * v.z + v.w * v.w;
            #pragma unroll
            for (int off = 16; off; off >>= 1)
                s += __shfl_down_sync(0xFFFFFFFFu, s, off);
            if (lane == 0) g_sq[row] = s;
        }
    } else if (b == lab_block) {
        if (tid == 0) s_is64 = 1;
        __syncthreads();
        for (int idx = tid; idx < n / 2; idx += 256)
            if (lab32[2 * idx + 1] != 0) atomicExch(&s_is64, 0);
        __syncthreads();
        const bool is64 = (s_is64 != 0);
        for (int i2 = tid; i2 < n; i2 += 256)
            g_lab[i2] = is64 ? lab32[2 * i2] : lab32[i2];
    }

    // ================= grid barrier =================
    __threadfence();
    __syncthreads();
    if (tid == 0) {
        atomicAdd(&g_bar1, 1);
        volatile int* vb = &g_bar1;
        while (*vb < GRID) { }
    }
    __syncthreads();

    // ================= phase 2: anchors =================
    float* pos_d = As;
    float lsum = 0.f;
    int   lcnt = 0;
    int   vtot = 0;

    for (int i = b; i < n; i += GRID) {
        const int   li  = g_lab[i];
        const float sqi = g_sq[i];
        const float* __restrict__ drow = &g_dot[(size_t)i * n];

        float nk0 = BIGF, nk1 = BIGF, nk2 = BIGF;
        float pv0 = 0.f, pv1 = 0.f, pv2 = 0.f;
        bool  ip0 = false, ip1 = false, ip2 = false;
        {
            int j = tid;
            float dv = sqrtf(fmaxf(sqi + g_sq[j] - 2.0f * drow[j], 0.0f));
            bool same = (g_lab[j] == li);
            nk0 = same ? BIGF : dv;
            ip0 = same && (j != i);
            pv0 = dv + MARGIN;
        }
        {
            int j = tid + 256;
            float dv = sqrtf(fmaxf(sqi + g_sq[j] - 2.0f * drow[j], 0.0f));
            bool same = (g_lab[j] == li);
            nk1 = same ? BIGF : dv;
            ip1 = same && (j != i);
            pv1 = dv + MARGIN;
        }
        if (tid + 512 < n) {
            int j = tid + 512;
            float dv = sqrtf(fmaxf(sqi + g_sq[j] - 2.0f * drow[j], 0.0f));
            bool same = (g_lab[j] == li);
            nk2 = same ? BIGF : dv;
            ip2 = same && (j != i);
            pv2 = dv + MARGIN;
        }

        __syncthreads();
        if (tid == 0) sp = 0;
        __syncthreads();

        {
            unsigned m = __ballot_sync(0xFFFFFFFFu, ip0);
            if (m) {
                int base = 0;
                if (lane == 0) base = atomicAdd(&sp, __popc(m));
                base = __shfl_sync(0xFFFFFFFFu, base, 0);
                if (ip0) pos_d[base + __popc(m & lmask_lt)] = pv0;
            }
        }
        {
            unsigned m = __ballot_sync(0xFFFFFFFFu, ip1);
            if (m) {
                int base = 0;
                if (lane == 0) base = atomicAdd(&sp, __popc(m));
                base = __shfl_sync(0xFFFFFFFFu, base, 0);
                if (ip1) pos_d[base + __popc(m & lmask_lt)] = pv1;
            }
        }
        {
            unsigned m = __ballot_sync(0xFFFFFFFFu, ip2);
            if (m) {
                int base = 0;
                if (lane == 0) base = atomicAdd(&sp, __popc(m));
                base = __shfl_sync(0xFFFFFFFFu, base, 0);
                if (ip2) pos_d[base + __popc(m & lmask_lt)] = pv2;
            }
        }
        __syncthreads();
        const int P = sp;
        if (tid < 4) pos_d[P + tid] = -BIGF;   // sentinel pad for 4-wide loop
        __syncthreads();

        // independent accumulator chains per j-slot
        float s0 = 0.f, s1 = 0.f, s2 = 0.f;
        int   c0 = 0,   c1 = 0,   c2 = 0;
        for (int jj = 0; jj < P; jj += 4) {
            float4 t = *(const float4*)&pos_d[jj];   // broadcast LDS.128
            if (nk0 < t.x) { s0 += t.x - nk0; c0++; }
            if (nk1 < t.x) { s1 += t.x - nk1; c1++; }
            if (nk2 < t.x) { s2 += t.x - nk2; c2++; }
            if (nk0 < t.y) { s0 += t.y - nk0; c0++; }
            if (nk1 < t.y) { s1 += t.y - nk1; c1++; }
            if (nk2 < t.y) { s2 += t.y - nk2; c2++; }
            if (nk0 < t.z) { s0 += t.z - nk0; c0++; }
            if (nk1 < t.z) { s1 += t.z - nk1; c1++; }
            if (nk2 < t.z) { s2 += t.z - nk2; c2++; }
            if (nk0 < t.w) { s0 += t.w - nk0; c0++; }
            if (nk1 < t.w) { s1 += t.w - nk1; c1++; }
            if (nk2 < t.w) { s2 += t.w - nk2; c2++; }
        }
        lsum += s0 + s1 + s2;
        lcnt += c0 + c1 + c2;
        vtot += P * (n - 1 - P);
    }

    // block reduce
    #pragma unroll
    for (int off = 16; off; off >>= 1) {
        lsum += __shfl_down_sync(0xFFFFFFFFu, lsum, off);
        lcnt += __shfl_down_sync(0xFFFFFFFFu, lcnt, off);
    }
    if (lane == 0) { wsum[wid] = lsum; wcnt[wid] = lcnt; }
    __syncthreads();
    if (tid == 0) {
        float s = 0.f; int c = 0;
        #pragma unroll
        for (int w = 0; w < 8; w++) { s += wsum[w]; c += wcnt[w]; }
        g_bsum[b] = s;
        g_bcnt[b] = c;
        g_bval[b] = vtot;
    }

    // ================= phase 3: last block finalizes =================
    __threadfence();
    __syncthreads();
    if (tid == 0) s_old = atomicAdd(&g_bar2, 1);
    __syncthreads();
    if (s_old == GRID - 1) {
        float s = 0.f; int c = 0, v = 0;
        for (int idx = tid; idx < GRID; idx += 256) {
            s += g_bsum[idx];
            c += g_bcnt[idx];
            v += g_bval[idx];
        }
        #pragma unroll
        for (int off = 16; off; off >>= 1) {
            s += __shfl_down_sync(0xFFFFFFFFu, s, off);
            c += __shfl_down_sync(0xFFFFFFFFu, c, off);
            v += __shfl_down_sync(0xFFFFFFFFu, v, off);
        }
        __shared__ float fs[8];
        __shared__ int   fc[8], fv[8];
        if (lane == 0) { fs[wid] = s; fc[wid] = c; fv[wid] = v; }
        __syncthreads();
        if (tid == 0) {
            float total = 0.f; int cnt = 0, val = 0;
            #pragma unroll
            for (int w = 0; w < 8; w++) { total += fs[w]; cnt += fc[w]; val += fv[w]; }
            float num_non   = (float)cnt;
            float num_valid = (float)val;
            out[0] = (cnt > 0) ? total / fmaxf(num_non, 1.0f) : 0.0f;
            out[1] = num_valid;
            out[2] = num_non;
            out[3] = num_non / (num_valid + 1e-16f);
            g_bar1 = 0;
            g_bar2 = 0;
            __threadfence();
        }
    }
}

extern "C" void kernel_launch(void* const* d_in, const int* in_sizes, int n_in,
                              void* d_out, int out_size) {
    const float* e   = (const float*)d_in[0];   // embeddings [8,80,128] fp32
    const int*   lab = (const int*)d_in[1];     // labels (int64 or int32 view)
    int n = in_sizes[1];                        // 640

    fused_triplet_kernel<<<GRID, 256>>>(e, lab, (float*)d_out, n);
}